// round 1
// baseline (speedup 1.0000x reference)
#include <cuda_runtime.h>
#include <math.h>

// Problem constants
#define Bc   128          // batch
#define Ac   196          // regions
#define Tt   21           // seq length
#define Tm   20           // timesteps (T-1)
#define Vc   7800         // vocab
#define Dc   300          // embed dim
#define Rc   512          // rnn size
#define Hc   512          // att hidden
#define FEc  2048         // att feat
#define Gc   2560         // 5*R gates
#define AP1  197          // A+1

// ---------------- device scratch (static, no allocation) ----------------
__device__ float g_v[(size_t)Bc*Ac*Rc];       // relu(att@ae_W^T+b)  [B,A,R]
__device__ float g_vemb[(size_t)Bc*Ac*Hc];    // v@c2a_W^T+b         [B,A,H]
__device__ float g_X[Tm*Bc*Dc];               // relu(E[tok])        [T,B,D]
__device__ float g_Xg[(size_t)Tm*Bc*Gc];      // X@w_ih^T            [T,B,5R]
__device__ float g_gates[Bc*Gc];              // per-step gates
__device__ float g_h[2][Bc*Rc];               // hidden ping-pong
__device__ float g_c[2][Bc*Rc];               // cell ping-pong
__device__ float g_sent[Bc*Rc];               // sentinel
__device__ float g_se[Bc*Hc];                 // sentinel embedding
__device__ float g_he[Bc*Hc];                 // h embedding
__device__ float g_cHat[Bc*Rc];               // context + hy
__device__ float g_Hout[Tm*Bc*Rc];            // all h_out rows

__device__ __forceinline__ float sigmoidf_(float x){ return 1.f/(1.f+expf(-x)); }

// ---------------- generic NT SGEMM tile: C[M,N] = A[M,K] @ B[N,K]^T ------
// bias[N] optional, addend[M,N] optional, act: 0 none / 1 relu / 2 tanh,
// remap: write C at [(r%128)*Tm + r/128][c] instead of [r][c] (for output layout)
template<int BM,int BN,int BK,int TM,int TN>
__device__ __forceinline__ void gemm_tile(
    const float* __restrict__ A, const float* __restrict__ Bw,
    float* __restrict__ C, const float* __restrict__ bias,
    const float* __restrict__ addend,
    int M, int N, int K, int act, int remap, int row0, int col0)
{
    constexpr int THREADS = (BM/TM)*(BN/TN);
    __shared__ float As[BK][BM+1];
    __shared__ float Bs[BK][BN+1];
    const int tid = threadIdx.x;
    const int tx  = tid % (BN/TN);
    const int ty  = tid / (BN/TN);

    float acc[TM][TN];
    #pragma unroll
    for (int i=0;i<TM;i++)
        #pragma unroll
        for (int j=0;j<TN;j++) acc[i][j] = 0.f;

    for (int k0=0;k0<K;k0+=BK){
        // coalesced loads: consecutive tids read consecutive k (contiguous in gmem)
        for (int i=tid;i<BM*BK;i+=THREADS){
            int r=i/BK, c=i%BK; int gr=row0+r, gk=k0+c;
            As[c][r] = (gr<M && gk<K) ? A[(size_t)gr*K+gk] : 0.f;
        }
        for (int i=tid;i<BN*BK;i+=THREADS){
            int r=i/BK, c=i%BK; int gn=col0+r, gk=k0+c;
            Bs[c][r] = (gn<N && gk<K) ? Bw[(size_t)gn*K+gk] : 0.f;
        }
        __syncthreads();
        #pragma unroll
        for (int kk=0;kk<BK;kk++){
            float ra[TM], rb[TN];
            #pragma unroll
            for (int i=0;i<TM;i++) ra[i] = As[kk][ty*TM+i];
            #pragma unroll
            for (int j=0;j<TN;j++) rb[j] = Bs[kk][tx*TN+j];
            #pragma unroll
            for (int i=0;i<TM;i++)
                #pragma unroll
                for (int j=0;j<TN;j++) acc[i][j] += ra[i]*rb[j];
        }
        __syncthreads();
    }

    #pragma unroll
    for (int i=0;i<TM;i++){
        int r = row0 + ty*TM + i;
        if (r >= M) continue;
        #pragma unroll
        for (int j=0;j<TN;j++){
            int c = col0 + tx*TN + j;
            if (c >= N) continue;
            float val = acc[i][j];
            if (bias)   val += bias[c];
            if (addend) val += addend[(size_t)r*N + c];
            if (act==1) val = fmaxf(val, 0.f);
            else if (act==2) val = tanhf(val);
            size_t o;
            if (remap){ int b = r & (Bc-1); int t = r >> 7; o = ((size_t)b*Tm + t)*N + c; }
            else o = (size_t)r*N + c;
            C[o] = val;
        }
    }
}

template<int BM,int BN,int BK,int TM,int TN>
__global__ void sgemm_nt(const float* __restrict__ A, const float* __restrict__ Bw,
                         float* __restrict__ C, const float* __restrict__ bias,
                         const float* __restrict__ addend,
                         int M,int N,int K,int act,int remap){
    gemm_tile<BM,BN,BK,TM,TN>(A,Bw,C,bias,addend,M,N,K,act,remap,
                              blockIdx.y*BM, blockIdx.x*BN);
}

// sent_emb = sentinel@se_W^T+b  |  h_emb = hy@ho_W^T+b  (one launch, 32 blocks)
__global__ void attemb_kernel(const float* __restrict__ se_W, const float* __restrict__ se_b,
                              const float* __restrict__ ho_W, const float* __restrict__ ho_b,
                              int pout){
    int half = blockIdx.x >> 4;
    int col0 = (blockIdx.x & 15) * 32;
    const float* A    = half ? g_h[pout] : g_sent;
    const float* Bw   = half ? ho_W     : se_W;
    const float* bias = half ? ho_b     : se_b;
    float*       C    = half ? g_he     : g_se;
    gemm_tile<128,32,32,8,2>(A,Bw,C,bias,nullptr,Bc,Hc,Rc,0,0,0,col0);
}

// ---------------- small kernels ----------------
__global__ void zero_state(){
    int i = blockIdx.x*blockDim.x + threadIdx.x;
    if (i < Bc*Rc){ g_h[0][i]=0.f; g_c[0][i]=0.f; }
}

__global__ void embed_relu(const float* __restrict__ E, const int* __restrict__ seq){
    int idx = blockIdx.x*blockDim.x + threadIdx.x;
    if (idx >= Tm*Bc*Dc) return;
    int d = idx % Dc;
    int b = (idx / Dc) % Bc;
    int t = idx / (Dc*Bc);
    int tok = seq[b*Tt + t];                 // tokens[t][b] = seq[b, t]
    g_X[idx] = fmaxf(E[(size_t)tok*Dc + d], 0.f);
}

__global__ void lstm_pointwise(int pin, int pout){
    int idx = blockIdx.x*blockDim.x + threadIdx.x;
    if (idx >= Bc*Rc) return;
    int b = idx >> 9;            // /512
    int r = idx & (Rc-1);
    const float* g = g_gates + b*Gc;
    float ig = sigmoidf_(g[r]);
    float fg = sigmoidf_(g[Rc   + r]);
    float gg = tanhf    (g[2*Rc + r]);
    float og = sigmoidf_(g[3*Rc + r]);
    float sg = sigmoidf_(g[4*Rc + r]);
    float cy = tanhf(fg * g_c[pin][idx] + ig * gg);
    g_c[pout][idx]  = cy;
    g_h[pout][idx]  = og * cy;
    g_sent[idx]     = sg * cy;
}

// adaptive attention: logits over [sentinel; regions] -> softmax -> context (+hy)
__global__ void att_ctx(const float* __restrict__ al_W, const float* __restrict__ al_b,
                        int pout){
    int b   = blockIdx.x;
    int tid = threadIdx.x;                   // 512 threads
    __shared__ float sh_he[Hc];
    __shared__ float sh_al[Hc];
    __shared__ float sh_l[AP1];
    __shared__ float red[512];

    sh_he[tid] = g_he[b*Hc + tid];
    sh_al[tid] = al_W[tid];
    __syncthreads();

    int warp = tid >> 5, lane = tid & 31;
    float alb = al_b[0];
    for (int j = warp; j < AP1; j += 16){
        const float* src = (j==0) ? (g_se + b*Hc)
                                  : (g_vemb + ((size_t)b*Ac + (j-1))*Hc);
        float s = 0.f;
        #pragma unroll 4
        for (int h = lane; h < Hc; h += 32)
            s += tanhf(src[h] + sh_he[h]) * sh_al[h];
        #pragma unroll
        for (int o=16;o;o>>=1) s += __shfl_xor_sync(0xffffffffu, s, o);
        if (lane==0) sh_l[j] = s + alb;
    }
    __syncthreads();

    // softmax over 197
    float m = (tid < AP1) ? sh_l[tid] : -1e30f;
    red[tid] = m; __syncthreads();
    for (int s=256;s>0;s>>=1){ if (tid<s) red[tid]=fmaxf(red[tid],red[tid+s]); __syncthreads(); }
    float mx = red[0]; __syncthreads();
    float e = (tid < AP1) ? expf(sh_l[tid]-mx) : 0.f;
    red[tid] = e; __syncthreads();
    for (int s=256;s>0;s>>=1){ if (tid<s) red[tid]+=red[tid+s]; __syncthreads(); }
    float inv = 1.f/red[0]; __syncthreads();
    if (tid < AP1) sh_l[tid] = e*inv;
    __syncthreads();

    // cHat[b,r] + hy[b,r]
    float acc = sh_l[0] * g_sent[b*Rc + tid];
    const float* vb = g_v + (size_t)b*Ac*Rc;
    #pragma unroll 4
    for (int a=0;a<Ac;a++) acc += sh_l[a+1] * vb[a*Rc + tid];
    g_cHat[b*Rc + tid] = acc + g_h[pout][b*Rc + tid];
}

__global__ void logsoftmax_kernel(float* __restrict__ out){
    float* x = out + (size_t)blockIdx.x * Vc;   // rows are (b,t), contiguous
    int tid = threadIdx.x;                      // 256
    __shared__ float red[256];
    float m = -1e30f;
    for (int i=tid;i<Vc;i+=256) m = fmaxf(m, x[i]);
    red[tid]=m; __syncthreads();
    for (int s=128;s>0;s>>=1){ if(tid<s) red[tid]=fmaxf(red[tid],red[tid+s]); __syncthreads(); }
    float mx = red[0]; __syncthreads();
    float ssum = 0.f;
    for (int i=tid;i<Vc;i+=256) ssum += expf(x[i]-mx);
    red[tid]=ssum; __syncthreads();
    for (int s=128;s>0;s>>=1){ if(tid<s) red[tid]+=red[tid+s]; __syncthreads(); }
    float lse = mx + logf(red[0]); __syncthreads();
    for (int i=tid;i<Vc;i+=256) x[i] -= lse;
}

// ---------------- host launcher ----------------
extern "C" void kernel_launch(void* const* d_in, const int* in_sizes, int n_in,
                              void* d_out, int out_size){
    const float* att   = (const float*)d_in[0];
    const int*   seq   = (const int*)  d_in[1];
    const float* E     = (const float*)d_in[2];
    const float* w_ih  = (const float*)d_in[3];
    const float* w_hh  = (const float*)d_in[4];
    const float* ae_W  = (const float*)d_in[5];
    const float* ae_b  = (const float*)d_in[6];
    const float* c2a_W = (const float*)d_in[7];
    const float* c2a_b = (const float*)d_in[8];
    const float* se_W  = (const float*)d_in[9];
    const float* se_b  = (const float*)d_in[10];
    const float* ho_W  = (const float*)d_in[11];
    const float* ho_b  = (const float*)d_in[12];
    const float* al_W  = (const float*)d_in[13];
    const float* al_b  = (const float*)d_in[14];
    const float* a2h_W = (const float*)d_in[15];
    const float* a2h_b = (const float*)d_in[16];
    const float* lg_W  = (const float*)d_in[17];
    const float* lg_b  = (const float*)d_in[18];
    float* out = (float*)d_out;

    float *pv,*pvemb,*pX,*pXg,*pgates,*pH,*pcHat,*pHout;
    cudaGetSymbolAddress((void**)&pv,    g_v);
    cudaGetSymbolAddress((void**)&pvemb, g_vemb);
    cudaGetSymbolAddress((void**)&pX,    g_X);
    cudaGetSymbolAddress((void**)&pXg,   g_Xg);
    cudaGetSymbolAddress((void**)&pgates,g_gates);
    cudaGetSymbolAddress((void**)&pH,    g_h);
    cudaGetSymbolAddress((void**)&pcHat, g_cHat);
    cudaGetSymbolAddress((void**)&pHout, g_Hout);

    zero_state<<<(Bc*Rc+255)/256,256>>>();
    embed_relu<<<(Tm*Bc*Dc+255)/256,256>>>(E, seq);

    // Hoisted big GEMMs
    sgemm_nt<128,128,32,8,8><<<dim3((Rc+127)/128,(Bc*Ac+127)/128),256>>>(
        att, ae_W, pv, ae_b, nullptr, Bc*Ac, Rc, FEc, /*relu*/1, 0);
    sgemm_nt<128,128,32,8,8><<<dim3((Hc+127)/128,(Bc*Ac+127)/128),256>>>(
        pv, c2a_W, pvemb, c2a_b, nullptr, Bc*Ac, Hc, Rc, 0, 0);
    // All-steps input-gate GEMM (batched over time)
    sgemm_nt<128,128,32,8,8><<<dim3((Gc+127)/128,(Tm*Bc+127)/128),256>>>(
        pX, w_ih, pXg, nullptr, nullptr, Tm*Bc, Gc, Dc, 0, 0);

    // Sequential recurrence (hy,cy carry only; h_out buffered)
    for (int t=0;t<Tm;t++){
        int pin = t & 1, pout = pin ^ 1;
        // gates = Xg[t] + hx @ w_hh^T
        sgemm_nt<128,32,32,8,2><<<dim3(Gc/32,1),256>>>(
            pH + (size_t)pin*Bc*Rc, w_hh, pgates, nullptr,
            pXg + (size_t)t*Bc*Gc, Bc, Gc, Rc, 0, 0);
        lstm_pointwise<<<(Bc*Rc+255)/256,256>>>(pin, pout);
        attemb_kernel<<<32,256>>>(se_W, se_b, ho_W, ho_b, pout);
        att_ctx<<<Bc,512>>>(al_W, al_b, pout);
        // h_out = tanh((cHat+hy)@a2h_W^T + b)  -> Hout[t]
        sgemm_nt<128,32,32,8,2><<<dim3(Rc/32,1),256>>>(
            pcHat, a2h_W, pHout + (size_t)t*Bc*Rc, a2h_b, nullptr,
            Bc, Rc, Rc, /*tanh*/2, 0);
    }

    // One batched vocab projection for all (t,b), written directly in [b,t,v] layout
    sgemm_nt<128,128,32,8,8><<<dim3((Vc+127)/128,(Tm*Bc+127)/128),256>>>(
        pHout, lg_W, out, lg_b, nullptr, Tm*Bc, Vc, Rc, 0, /*remap*/1);
    logsoftmax_kernel<<<Bc*Tm,256>>>(out);
}

// round 2
// speedup vs baseline: 1.6921x; 1.6921x over previous
#include <cuda_runtime.h>
#include <math.h>
#include <mma.h>
using namespace nvcuda;

// Problem constants
#define Bc   128          // batch
#define Ac   196          // regions
#define Tt   21           // seq length
#define Tm   20           // timesteps (T-1)
#define Vc   7800         // vocab
#define Dc   300          // embed dim
#define Rc   512          // rnn size
#define Hc   512          // att hidden
#define FEc  2048         // att feat
#define Gc   2560         // 5*R gates
#define AP1  197          // A+1

// GEMM tile config (TF32 WMMA)
#define BM   128
#define BN   64
#define BK   32
#define BKP  36           // padded K stride in smem (mult of 4)
#define CP   72           // padded N stride for epilogue staging
#define SMEM_FLOATS 9216  // max( (BM+BN)*BKP = 6912 , BM*CP = 9216 )

// ---------------- device scratch (static, no allocation) ----------------
__device__ float g_v[(size_t)Bc*Ac*Rc];       // relu(att@ae_W^T+b)  [B,A,R]
__device__ float g_vemb[(size_t)Bc*Ac*Hc];    // v@c2a_W^T+b         [B,A,H]
__device__ float g_X[Tm*Bc*Dc];               // relu(E[tok])        [T,B,D]
__device__ float g_Xg[(size_t)Tm*Bc*Gc];      // X@w_ih^T            [T,B,5R]
__device__ float g_gates[Bc*Gc];              // per-step gates
__device__ float g_h[2][Bc*Rc];               // hidden ping-pong
__device__ float g_c[2][Bc*Rc];               // cell ping-pong
__device__ float g_sent[Bc*Rc];               // sentinel
__device__ float g_se[Bc*Hc];                 // sentinel embedding
__device__ float g_he[Bc*Hc];                 // h embedding
__device__ float g_cHat[Bc*Rc];               // context + hy
__device__ float g_Hout[Tm*Bc*Rc];            // all h_out rows

__device__ __forceinline__ float sigmoidf_(float x){ return 1.f/(1.f+expf(-x)); }

// ---------------- TF32 WMMA NT GEMM tile: C[M,N] = A[M,K] @ B[N,K]^T -----
// bias[N] optional, addend[M,N] optional, act: 0 none / 1 relu / 2 tanh,
// remap: write C at [(r%128)*Tm + r/128][c] (output [b,t,v] layout)
__device__ __forceinline__ void tgemm_tile(
    const float* __restrict__ A, const float* __restrict__ Bw,
    float* __restrict__ C, const float* __restrict__ bias,
    const float* __restrict__ addend,
    int M, int N, int K, int act, int remap, int row0, int col0,
    float* smem)
{
    float* As = smem;                 // [BM][BKP]
    float* Bs = smem + BM*BKP;        // [BN][BKP]
    const int tid = threadIdx.x;      // 256 threads, 8 warps
    const int wid = tid >> 5;
    const int warp_m = wid & 3;       // 4 warps along M (32 rows each)
    const int warp_n = wid >> 2;      // 2 warps along N (32 cols each)

    wmma::fragment<wmma::accumulator,16,16,8,float> acc[2][2];
    #pragma unroll
    for (int mi=0;mi<2;mi++)
        #pragma unroll
        for (int ni=0;ni<2;ni++) wmma::fill_fragment(acc[mi][ni], 0.f);

    for (int k0=0;k0<K;k0+=BK){
        // Stage A tile: BM*BK = 4096 floats = 1024 float4 (4 per thread)
        #pragma unroll
        for (int i=0;i<4;i++){
            int v = tid + i*256;
            int r = v >> 3;            // /(BK/4)
            int c4 = (v & 7) << 2;
            int gr = row0 + r, gk = k0 + c4;
            float4 val = make_float4(0.f,0.f,0.f,0.f);
            if (gr < M && gk < K) val = *(const float4*)(A + (size_t)gr*K + gk);
            *(float4*)(As + r*BKP + c4) = val;
        }
        // Stage B tile: BN*BK = 2048 floats = 512 float4 (2 per thread)
        #pragma unroll
        for (int i=0;i<2;i++){
            int v = tid + i*256;
            int r = v >> 3;
            int c4 = (v & 7) << 2;
            int gn = col0 + r, gk = k0 + c4;
            float4 val = make_float4(0.f,0.f,0.f,0.f);
            if (gn < N && gk < K) val = *(const float4*)(Bw + (size_t)gn*K + gk);
            *(float4*)(Bs + r*BKP + c4) = val;
        }
        __syncthreads();
        #pragma unroll
        for (int ks=0;ks<BK/8;ks++){
            wmma::fragment<wmma::matrix_a,16,16,8,wmma::precision::tf32,wmma::row_major> af[2];
            wmma::fragment<wmma::matrix_b,16,16,8,wmma::precision::tf32,wmma::col_major> bf[2];
            #pragma unroll
            for (int mi=0;mi<2;mi++){
                wmma::load_matrix_sync(af[mi], As + (warp_m*32+mi*16)*BKP + ks*8, BKP);
                #pragma unroll
                for (int e=0;e<af[mi].num_elements;e++)
                    af[mi].x[e] = wmma::__float_to_tf32(af[mi].x[e]);
            }
            #pragma unroll
            for (int ni=0;ni<2;ni++){
                wmma::load_matrix_sync(bf[ni], Bs + (warp_n*32+ni*16)*BKP + ks*8, BKP);
                #pragma unroll
                for (int e=0;e<bf[ni].num_elements;e++)
                    bf[ni].x[e] = wmma::__float_to_tf32(bf[ni].x[e]);
            }
            #pragma unroll
            for (int mi=0;mi<2;mi++)
                #pragma unroll
                for (int ni=0;ni<2;ni++)
                    wmma::mma_sync(acc[mi][ni], af[mi], bf[ni], acc[mi][ni]);
        }
        __syncthreads();
    }

    // Stage C through smem (reuses As/Bs space) for guarded epilogue
    float* Cs = smem;                 // [BM][CP]
    #pragma unroll
    for (int mi=0;mi<2;mi++)
        #pragma unroll
        for (int ni=0;ni<2;ni++)
            wmma::store_matrix_sync(Cs + (warp_m*32+mi*16)*CP + warp_n*32+ni*16,
                                    acc[mi][ni], CP, wmma::mem_row_major);
    __syncthreads();

    for (int i=tid;i<BM*BN;i+=256){
        int r=i/BN, c=i%BN;
        int gr=row0+r, gc=col0+c;
        if (gr>=M || gc>=N) continue;
        float val = Cs[r*CP + c];
        if (bias)   val += bias[gc];
        if (addend) val += addend[(size_t)gr*N + gc];
        if (act==1) val = fmaxf(val, 0.f);
        else if (act==2) val = tanhf(val);
        size_t o;
        if (remap){ int b = gr & (Bc-1); int t = gr >> 7; o = ((size_t)b*Tm + t)*N + gc; }
        else o = (size_t)gr*N + gc;
        C[o] = val;
    }
}

__global__ __launch_bounds__(256) void tgemm(
    const float* __restrict__ A, const float* __restrict__ Bw,
    float* __restrict__ C, const float* __restrict__ bias,
    const float* __restrict__ addend,
    int M,int N,int K,int act,int remap)
{
    __shared__ __align__(128) float smem[SMEM_FLOATS];
    tgemm_tile(A,Bw,C,bias,addend,M,N,K,act,remap,
               blockIdx.y*BM, blockIdx.x*BN, smem);
}

// sent_emb = sentinel@se_W^T+b  |  h_emb = hy@ho_W^T+b  (one launch, 16 blocks)
__global__ __launch_bounds__(256) void attemb_kernel(
    const float* __restrict__ se_W, const float* __restrict__ se_b,
    const float* __restrict__ ho_W, const float* __restrict__ ho_b,
    int pout)
{
    __shared__ __align__(128) float smem[SMEM_FLOATS];
    int half = blockIdx.x >> 3;            // 8 col-tiles of 64 per half
    int col0 = (blockIdx.x & 7) * BN;
    const float* A    = half ? g_h[pout] : g_sent;
    const float* Bw   = half ? ho_W     : se_W;
    const float* bias = half ? ho_b     : se_b;
    float*       C    = half ? g_he     : g_se;
    tgemm_tile(A,Bw,C,bias,nullptr,Bc,Hc,Rc,0,0,0,col0,smem);
}

// ---------------- small kernels ----------------
__global__ void zero_state(){
    int i = blockIdx.x*blockDim.x + threadIdx.x;
    if (i < Bc*Rc){ g_h[0][i]=0.f; g_c[0][i]=0.f; }
}

__global__ void embed_relu(const float* __restrict__ E, const int* __restrict__ seq){
    int idx = blockIdx.x*blockDim.x + threadIdx.x;
    if (idx >= Tm*Bc*Dc) return;
    int d = idx % Dc;
    int b = (idx / Dc) % Bc;
    int t = idx / (Dc*Bc);
    int tok = seq[b*Tt + t];                 // tokens[t][b] = seq[b, t]
    g_X[idx] = fmaxf(E[(size_t)tok*Dc + d], 0.f);
}

__global__ void lstm_pointwise(int pin, int pout){
    int idx = blockIdx.x*blockDim.x + threadIdx.x;
    if (idx >= Bc*Rc) return;
    int b = idx >> 9;            // /512
    int r = idx & (Rc-1);
    const float* g = g_gates + b*Gc;
    float ig = sigmoidf_(g[r]);
    float fg = sigmoidf_(g[Rc   + r]);
    float gg = tanhf    (g[2*Rc + r]);
    float og = sigmoidf_(g[3*Rc + r]);
    float sg = sigmoidf_(g[4*Rc + r]);
    float cy = tanhf(fg * g_c[pin][idx] + ig * gg);
    g_c[pout][idx]  = cy;
    g_h[pout][idx]  = og * cy;
    g_sent[idx]     = sg * cy;
}

// adaptive attention: logits over [sentinel; regions] -> softmax -> context (+hy)
__global__ void att_ctx(const float* __restrict__ al_W, const float* __restrict__ al_b,
                        int pout){
    int b   = blockIdx.x;
    int tid = threadIdx.x;                   // 512 threads
    __shared__ float sh_he[Hc];
    __shared__ float sh_al[Hc];
    __shared__ float sh_l[AP1];
    __shared__ float red[512];

    sh_he[tid] = g_he[b*Hc + tid];
    sh_al[tid] = al_W[tid];
    __syncthreads();

    int warp = tid >> 5, lane = tid & 31;
    float alb = al_b[0];
    for (int j = warp; j < AP1; j += 16){
        const float* src = (j==0) ? (g_se + b*Hc)
                                  : (g_vemb + ((size_t)b*Ac + (j-1))*Hc);
        float s = 0.f;
        #pragma unroll 4
        for (int h = lane; h < Hc; h += 32)
            s += tanhf(src[h] + sh_he[h]) * sh_al[h];
        #pragma unroll
        for (int o=16;o;o>>=1) s += __shfl_xor_sync(0xffffffffu, s, o);
        if (lane==0) sh_l[j] = s + alb;
    }
    __syncthreads();

    // softmax over 197
    float m = (tid < AP1) ? sh_l[tid] : -1e30f;
    red[tid] = m; __syncthreads();
    for (int s=256;s>0;s>>=1){ if (tid<s) red[tid]=fmaxf(red[tid],red[tid+s]); __syncthreads(); }
    float mx = red[0]; __syncthreads();
    float e = (tid < AP1) ? expf(sh_l[tid]-mx) : 0.f;
    red[tid] = e; __syncthreads();
    for (int s=256;s>0;s>>=1){ if (tid<s) red[tid]+=red[tid+s]; __syncthreads(); }
    float inv = 1.f/red[0]; __syncthreads();
    if (tid < AP1) sh_l[tid] = e*inv;
    __syncthreads();

    // cHat[b,r] + hy[b,r]
    float acc = sh_l[0] * g_sent[b*Rc + tid];
    const float* vb = g_v + (size_t)b*Ac*Rc;
    #pragma unroll 4
    for (int a=0;a<Ac;a++) acc += sh_l[a+1] * vb[a*Rc + tid];
    g_cHat[b*Rc + tid] = acc + g_h[pout][b*Rc + tid];
}

__global__ void logsoftmax_kernel(float* __restrict__ out){
    float* x = out + (size_t)blockIdx.x * Vc;   // rows are (b,t), contiguous
    int tid = threadIdx.x;                      // 256
    __shared__ float red[256];
    float m = -1e30f;
    for (int i=tid;i<Vc;i+=256) m = fmaxf(m, x[i]);
    red[tid]=m; __syncthreads();
    for (int s=128;s>0;s>>=1){ if(tid<s) red[tid]=fmaxf(red[tid],red[tid+s]); __syncthreads(); }
    float mx = red[0]; __syncthreads();
    float ssum = 0.f;
    for (int i=tid;i<Vc;i+=256) ssum += expf(x[i]-mx);
    red[tid]=ssum; __syncthreads();
    for (int s=128;s>0;s>>=1){ if(tid<s) red[tid]+=red[tid+s]; __syncthreads(); }
    float lse = mx + logf(red[0]); __syncthreads();
    for (int i=tid;i<Vc;i+=256) x[i] -= lse;
}

// ---------------- host launcher ----------------
extern "C" void kernel_launch(void* const* d_in, const int* in_sizes, int n_in,
                              void* d_out, int out_size){
    const float* att   = (const float*)d_in[0];
    const int*   seq   = (const int*)  d_in[1];
    const float* E     = (const float*)d_in[2];
    const float* w_ih  = (const float*)d_in[3];
    const float* w_hh  = (const float*)d_in[4];
    const float* ae_W  = (const float*)d_in[5];
    const float* ae_b  = (const float*)d_in[6];
    const float* c2a_W = (const float*)d_in[7];
    const float* c2a_b = (const float*)d_in[8];
    const float* se_W  = (const float*)d_in[9];
    const float* se_b  = (const float*)d_in[10];
    const float* ho_W  = (const float*)d_in[11];
    const float* ho_b  = (const float*)d_in[12];
    const float* al_W  = (const float*)d_in[13];
    const float* al_b  = (const float*)d_in[14];
    const float* a2h_W = (const float*)d_in[15];
    const float* a2h_b = (const float*)d_in[16];
    const float* lg_W  = (const float*)d_in[17];
    const float* lg_b  = (const float*)d_in[18];
    float* out = (float*)d_out;

    float *pv,*pvemb,*pX,*pXg,*pgates,*pH,*pcHat,*pHout;
    cudaGetSymbolAddress((void**)&pv,    g_v);
    cudaGetSymbolAddress((void**)&pvemb, g_vemb);
    cudaGetSymbolAddress((void**)&pX,    g_X);
    cudaGetSymbolAddress((void**)&pXg,   g_Xg);
    cudaGetSymbolAddress((void**)&pgates,g_gates);
    cudaGetSymbolAddress((void**)&pH,    g_h);
    cudaGetSymbolAddress((void**)&pcHat, g_cHat);
    cudaGetSymbolAddress((void**)&pHout, g_Hout);

    zero_state<<<(Bc*Rc+255)/256,256>>>();
    embed_relu<<<(Tm*Bc*Dc+255)/256,256>>>(E, seq);

    // Hoisted big GEMMs (TF32 tensor cores)
    tgemm<<<dim3(Rc/BN,(Bc*Ac)/BM),256>>>(att, ae_W, pv, ae_b, nullptr,
                                          Bc*Ac, Rc, FEc, /*relu*/1, 0);
    tgemm<<<dim3(Hc/BN,(Bc*Ac)/BM),256>>>(pv, c2a_W, pvemb, c2a_b, nullptr,
                                          Bc*Ac, Hc, Rc, 0, 0);
    tgemm<<<dim3(Gc/BN,(Tm*Bc)/BM),256>>>(pX, w_ih, pXg, nullptr, nullptr,
                                          Tm*Bc, Gc, Dc, 0, 0);

    // Sequential recurrence (hy,cy carry only; h_out buffered)
    for (int t=0;t<Tm;t++){
        int pin = t & 1, pout = pin ^ 1;
        // gates = Xg[t] + hx @ w_hh^T
        tgemm<<<dim3(Gc/BN,1),256>>>(pH + (size_t)pin*Bc*Rc, w_hh, pgates,
                                     nullptr, pXg + (size_t)t*Bc*Gc,
                                     Bc, Gc, Rc, 0, 0);
        lstm_pointwise<<<(Bc*Rc+255)/256,256>>>(pin, pout);
        attemb_kernel<<<16,256>>>(se_W, se_b, ho_W, ho_b, pout);
        att_ctx<<<Bc,512>>>(al_W, al_b, pout);
        // h_out = tanh((cHat+hy)@a2h_W^T + b)  -> Hout[t]
        tgemm<<<dim3(Rc/BN,1),256>>>(pcHat, a2h_W, pHout + (size_t)t*Bc*Rc,
                                     a2h_b, nullptr, Bc, Rc, Rc, /*tanh*/2, 0);
    }

    // One batched vocab projection for all (t,b), written in [b,t,v] layout
    tgemm<<<dim3((Vc+BN-1)/BN,(Tm*Bc)/BM),256>>>(pHout, lg_W, out, lg_b, nullptr,
                                                 Tm*Bc, Vc, Rc, 0, /*remap*/1);
    logsoftmax_kernel<<<Bc*Tm,256>>>(out);
}

// round 5
// speedup vs baseline: 1.7850x; 1.0549x over previous
#include <cuda_runtime.h>
#include <math.h>
#include <mma.h>
using namespace nvcuda;

// Problem constants
#define Bc   128          // batch
#define Ac   196          // regions
#define Tt   21           // seq length
#define Tm   20           // timesteps (T-1)
#define Vc   7800         // vocab
#define Dc   300          // embed dim
#define Rc   512          // rnn size
#define Hc   512          // att hidden
#define FEc  2048         // att feat
#define Gc   2560         // 5*R gates
#define AP1  197          // A+1

// GEMM tile config (TF32 WMMA)
#define BM   128
#define BN   64
#define BK   32
#define BKP  36
#define CP   72
#define SMEM_FLOATS 9216

// ---------------- device scratch (static, no allocation) ----------------
__device__ float g_v[(size_t)Bc*Ac*Rc];       // relu(att@ae_W^T+b)  [B,A,R]
__device__ float g_vemb[(size_t)Bc*Ac*Hc];    // v@c2a_W^T+b         [B,A,H]
__device__ float g_X[Tm*Bc*Dc];               // relu(E[tok])        [T,B,D]
__device__ float g_Xg[(size_t)Tm*Bc*Gc];      // X@w_ih^T            [T,B,5R]
__device__ float g_gates[Bc*Gc];              // per-step gates
__device__ float g_h[2][Bc*Rc];               // hidden ping-pong
__device__ float g_c[2][Bc*Rc];               // cell ping-pong
__device__ float g_Hout[Tm*Bc*Rc];            // all h_out rows
__device__ float g_seWt[Rc*Hc];               // se_W transposed [R,H]
__device__ float g_hoWt[Rc*Hc];               // ho_W transposed [R,H]
__device__ float g_a2hWt[Rc*Rc];              // a2h_W transposed [R,R]

__device__ __forceinline__ float sigmoidf_(float x){ return 1.f/(1.f+expf(-x)); }
__device__ __forceinline__ float tanh_fast(float x){
    float y; asm("tanh.approx.f32 %0, %1;" : "=f"(y) : "f"(x)); return y;
}

// ---------------- TF32 WMMA NT GEMM: C[M,N] = A[M,K] @ B[N,K]^T ----------
__device__ __forceinline__ void tgemm_tile(
    const float* __restrict__ A, const float* __restrict__ Bw,
    float* __restrict__ C, const float* __restrict__ bias,
    const float* __restrict__ addend,
    int M, int N, int K, int act, int remap, int row0, int col0,
    float* smem)
{
    float* As = smem;
    float* Bs = smem + BM*BKP;
    const int tid = threadIdx.x;
    const int wid = tid >> 5;
    const int warp_m = wid & 3;
    const int warp_n = wid >> 2;

    wmma::fragment<wmma::accumulator,16,16,8,float> acc[2][2];
    #pragma unroll
    for (int mi=0;mi<2;mi++)
        #pragma unroll
        for (int ni=0;ni<2;ni++) wmma::fill_fragment(acc[mi][ni], 0.f);

    for (int k0=0;k0<K;k0+=BK){
        #pragma unroll
        for (int i=0;i<4;i++){
            int v = tid + i*256;
            int r = v >> 3;
            int c4 = (v & 7) << 2;
            int gr = row0 + r, gk = k0 + c4;
            float4 val = make_float4(0.f,0.f,0.f,0.f);
            if (gr < M && gk < K) val = *(const float4*)(A + (size_t)gr*K + gk);
            *(float4*)(As + r*BKP + c4) = val;
        }
        #pragma unroll
        for (int i=0;i<2;i++){
            int v = tid + i*256;
            int r = v >> 3;
            int c4 = (v & 7) << 2;
            int gn = col0 + r, gk = k0 + c4;
            float4 val = make_float4(0.f,0.f,0.f,0.f);
            if (gn < N && gk < K) val = *(const float4*)(Bw + (size_t)gn*K + gk);
            *(float4*)(Bs + r*BKP + c4) = val;
        }
        __syncthreads();
        #pragma unroll
        for (int ks=0;ks<BK/8;ks++){
            wmma::fragment<wmma::matrix_a,16,16,8,wmma::precision::tf32,wmma::row_major> af[2];
            wmma::fragment<wmma::matrix_b,16,16,8,wmma::precision::tf32,wmma::col_major> bf[2];
            #pragma unroll
            for (int mi=0;mi<2;mi++){
                wmma::load_matrix_sync(af[mi], As + (warp_m*32+mi*16)*BKP + ks*8, BKP);
                #pragma unroll
                for (int e=0;e<af[mi].num_elements;e++)
                    af[mi].x[e] = wmma::__float_to_tf32(af[mi].x[e]);
            }
            #pragma unroll
            for (int ni=0;ni<2;ni++){
                wmma::load_matrix_sync(bf[ni], Bs + (warp_n*32+ni*16)*BKP + ks*8, BKP);
                #pragma unroll
                for (int e=0;e<bf[ni].num_elements;e++)
                    bf[ni].x[e] = wmma::__float_to_tf32(bf[ni].x[e]);
            }
            #pragma unroll
            for (int mi=0;mi<2;mi++)
                #pragma unroll
                for (int ni=0;ni<2;ni++)
                    wmma::mma_sync(acc[mi][ni], af[mi], bf[ni], acc[mi][ni]);
        }
        __syncthreads();
    }

    float* Cs = smem;
    #pragma unroll
    for (int mi=0;mi<2;mi++)
        #pragma unroll
        for (int ni=0;ni<2;ni++)
            wmma::store_matrix_sync(Cs + (warp_m*32+mi*16)*CP + warp_n*32+ni*16,
                                    acc[mi][ni], CP, wmma::mem_row_major);
    __syncthreads();

    for (int i=tid;i<BM*BN;i+=256){
        int r=i/BN, c=i%BN;
        int gr=row0+r, gc=col0+c;
        if (gr>=M || gc>=N) continue;
        float val = Cs[r*CP + c];
        if (bias)   val += bias[gc];
        if (addend) val += addend[(size_t)gr*N + gc];
        if (act==1) val = fmaxf(val, 0.f);
        else if (act==2) val = tanhf(val);
        size_t o;
        if (remap){ int b = gr & (Bc-1); int t = gr >> 7; o = ((size_t)b*Tm + t)*N + gc; }
        else o = (size_t)gr*N + gc;
        C[o] = val;
    }
}

__global__ __launch_bounds__(256) void tgemm(
    const float* __restrict__ A, const float* __restrict__ Bw,
    float* __restrict__ C, const float* __restrict__ bias,
    const float* __restrict__ addend,
    int M,int N,int K,int act,int remap)
{
    __shared__ __align__(128) float smem[SMEM_FLOATS];
    tgemm_tile(A,Bw,C,bias,addend,M,N,K,act,remap,
               blockIdx.y*BM, blockIdx.x*BN, smem);
}

// ---------------- one-time weight transposes (512x512 each) --------------
__global__ void transpose_w(const float* __restrict__ se_W,
                            const float* __restrict__ ho_W,
                            const float* __restrict__ a2h_W){
    __shared__ float tile[32][33];
    int which = blockIdx.z;
    const float* src = which==0 ? se_W : (which==1 ? ho_W : a2h_W);
    float* dst = which==0 ? g_seWt : (which==1 ? g_hoWt : g_a2hWt);
    int x0 = blockIdx.x*32, y0 = blockIdx.y*32;
    int tx = threadIdx.x, ty = threadIdx.y;
    // src[h][r], h = y, r = x
    tile[ty][tx] = src[(y0+ty)*Rc + x0+tx];
    __syncthreads();
    // dst[r][h]
    dst[(x0+ty)*Hc + y0+tx] = tile[tx][ty];
}

// ---------------- small kernels ----------------
__global__ void zero_state(){
    int i = blockIdx.x*blockDim.x + threadIdx.x;
    if (i < Bc*Rc){ g_h[0][i]=0.f; g_c[0][i]=0.f; }
}

__global__ void embed_relu(const float* __restrict__ E, const int* __restrict__ seq){
    int idx = blockIdx.x*blockDim.x + threadIdx.x;
    if (idx >= Tm*Bc*Dc) return;
    int d = idx % Dc;
    int b = (idx / Dc) % Bc;
    int t = idx / (Dc*Bc);
    int tok = seq[b*Tt + t];
    g_X[idx] = fmaxf(E[(size_t)tok*Dc + d], 0.f);
}

// ============ fused per-step kernel: one block per batch element =========
// Does: LSTM pointwise -> sent/h embeddings -> att logits (fast tanh) ->
//       softmax -> context -> a2h projection -> h_out
__global__ __launch_bounds__(512) void fused_step(
    const float* __restrict__ se_b, const float* __restrict__ ho_b,
    const float* __restrict__ al_W, const float* __restrict__ al_b,
    const float* __restrict__ a2h_b,
    int t, int pin, int pout)
{
    int b   = blockIdx.x;
    int tid = threadIdx.x;              // 512
    __shared__ float sh_hy[Rc];
    __shared__ float sh_sent[Rc];
    __shared__ float sh_he[Hc];
    __shared__ float sh_se[Hc];
    __shared__ float sh_al[Hc];
    __shared__ float sh_cv[Rc];
    __shared__ float sh_l[AP1];
    __shared__ float red[512];

    // --- 1. LSTM pointwise (thread = r) ---
    {
        const float* g = g_gates + b*Gc;
        int r = tid;
        float ig = sigmoidf_(g[r]);
        float fg = sigmoidf_(g[Rc   + r]);
        float gg = tanhf    (g[2*Rc + r]);
        float og = sigmoidf_(g[3*Rc + r]);
        float sg = sigmoidf_(g[4*Rc + r]);
        float cy = tanhf(fg * g_c[pin][b*Rc + r] + ig * gg);
        float hy = og * cy;
        float st = sg * cy;
        g_c[pout][b*Rc + r] = cy;
        g_h[pout][b*Rc + r] = hy;
        sh_hy[r]   = hy;
        sh_sent[r] = st;
        sh_al[r]   = al_W[r];
    }
    __syncthreads();

    // --- 2. embeddings: thread = h; coalesced via transposed weights ---
    {
        int h = tid;
        float accs = se_b[h];
        float acch = ho_b[h];
        #pragma unroll 8
        for (int r=0;r<Rc;r++){
            float ws = g_seWt[r*Hc + h];
            float wh = g_hoWt[r*Hc + h];
            accs += sh_sent[r] * ws;
            acch += sh_hy[r]   * wh;
        }
        sh_se[h] = accs;
        sh_he[h] = acch;
    }
    __syncthreads();

    // --- 3. attention logits over [sentinel; regions], fast tanh ---
    {
        int warp = tid >> 5, lane = tid & 31;
        float alb = al_b[0];
        for (int j = warp; j < AP1; j += 16){
            const float* src = (j==0) ? sh_se
                                      : (g_vemb + ((size_t)b*Ac + (j-1))*Hc);
            float s = 0.f;
            #pragma unroll 4
            for (int h = lane; h < Hc; h += 32)
                s += tanh_fast(src[h] + sh_he[h]) * sh_al[h];
            #pragma unroll
            for (int o=16;o;o>>=1) s += __shfl_xor_sync(0xffffffffu, s, o);
            if (lane==0) sh_l[j] = s + alb;
        }
    }
    __syncthreads();

    // --- 4. softmax over 197 ---
    {
        float m = (tid < AP1) ? sh_l[tid] : -1e30f;
        red[tid] = m; __syncthreads();
        for (int s=256;s>0;s>>=1){ if (tid<s) red[tid]=fmaxf(red[tid],red[tid+s]); __syncthreads(); }
        float mx = red[0]; __syncthreads();
        float e = (tid < AP1) ? expf(sh_l[tid]-mx) : 0.f;
        red[tid] = e; __syncthreads();
        for (int s=256;s>0;s>>=1){ if (tid<s) red[tid]+=red[tid+s]; __syncthreads(); }
        float inv = 1.f/red[0]; __syncthreads();
        if (tid < AP1) sh_l[tid] = e*inv;
    }
    __syncthreads();

    // --- 5. context + hy (thread = r) ---
    {
        int r = tid;
        float acc = sh_l[0] * sh_sent[r];
        const float* vb = g_v + (size_t)b*Ac*Rc + r;
        #pragma unroll 4
        for (int a=0;a<Ac;a++) acc += sh_l[a+1] * vb[(size_t)a*Rc];
        sh_cv[r] = acc + sh_hy[r];
    }
    __syncthreads();

    // --- 6. a2h projection + tanh -> h_out (thread = h) ---
    {
        int h = tid;
        float acc = a2h_b[h];
        #pragma unroll 8
        for (int r=0;r<Rc;r++)
            acc += sh_cv[r] * g_a2hWt[r*Rc + h];
        g_Hout[((size_t)t*Bc + b)*Rc + h] = tanhf(acc);
    }
}

__global__ void logsoftmax_kernel(float* __restrict__ out){
    float* x = out + (size_t)blockIdx.x * Vc;
    int tid = threadIdx.x;                      // 256
    __shared__ float red[256];
    float m = -1e30f;
    for (int i=tid;i<Vc;i+=256) m = fmaxf(m, x[i]);
    red[tid]=m; __syncthreads();
    for (int s=128;s>0;s>>=1){ if(tid<s) red[tid]=fmaxf(red[tid],red[tid+s]); __syncthreads(); }
    float mx = red[0]; __syncthreads();
    float ssum = 0.f;
    for (int i=tid;i<Vc;i+=256) ssum += expf(x[i]-mx);
    red[tid]=ssum; __syncthreads();
    for (int s=128;s>0;s>>=1){ if(tid<s) red[tid]+=red[tid+s]; __syncthreads(); }
    float lse = mx + logf(red[0]); __syncthreads();
    for (int i=tid;i<Vc;i+=256) x[i] -= lse;
}

// ---------------- host launcher ----------------
extern "C" void kernel_launch(void* const* d_in, const int* in_sizes, int n_in,
                              void* d_out, int out_size){
    const float* att   = (const float*)d_in[0];
    const int*   seq   = (const int*)  d_in[1];
    const float* E     = (const float*)d_in[2];
    const float* w_ih  = (const float*)d_in[3];
    const float* w_hh  = (const float*)d_in[4];
    const float* ae_W  = (const float*)d_in[5];
    const float* ae_b  = (const float*)d_in[6];
    const float* c2a_W = (const float*)d_in[7];
    const float* c2a_b = (const float*)d_in[8];
    const float* se_W  = (const float*)d_in[9];
    const float* se_b  = (const float*)d_in[10];
    const float* ho_W  = (const float*)d_in[11];
    const float* ho_b  = (const float*)d_in[12];
    const float* al_W  = (const float*)d_in[13];
    const float* al_b  = (const float*)d_in[14];
    const float* a2h_W = (const float*)d_in[15];
    const float* a2h_b = (const float*)d_in[16];
    const float* lg_W  = (const float*)d_in[17];
    const float* lg_b  = (const float*)d_in[18];
    float* out = (float*)d_out;

    float *pv,*pX,*pXg,*pgates,*pH,*pHout;
    cudaGetSymbolAddress((void**)&pv,    g_v);
    cudaGetSymbolAddress((void**)&pX,    g_X);
    cudaGetSymbolAddress((void**)&pXg,   g_Xg);
    cudaGetSymbolAddress((void**)&pgates,g_gates);
    cudaGetSymbolAddress((void**)&pH,    g_h);
    cudaGetSymbolAddress((void**)&pHout, g_Hout);
    float* pvemb; cudaGetSymbolAddress((void**)&pvemb, g_vemb);

    zero_state<<<(Bc*Rc+255)/256,256>>>();
    embed_relu<<<(Tm*Bc*Dc+255)/256,256>>>(E, seq);
    transpose_w<<<dim3(16,16,3),dim3(32,32)>>>(se_W, ho_W, a2h_W);

    // Hoisted big GEMMs (TF32 tensor cores)
    tgemm<<<dim3(Rc/BN,(Bc*Ac)/BM),256>>>(att, ae_W, pv, ae_b, nullptr,
                                          Bc*Ac, Rc, FEc, /*relu*/1, 0);
    tgemm<<<dim3(Hc/BN,(Bc*Ac)/BM),256>>>(pv, c2a_W, pvemb, c2a_b, nullptr,
                                          Bc*Ac, Hc, Rc, 0, 0);
    tgemm<<<dim3(Gc/BN,(Tm*Bc)/BM),256>>>(pX, w_ih, pXg, nullptr, nullptr,
                                          Tm*Bc, Gc, Dc, 0, 0);

    // Sequential recurrence: 2 launches per step
    for (int t=0;t<Tm;t++){
        int pin = t & 1, pout = pin ^ 1;
        tgemm<<<dim3(Gc/BN,1),256>>>(pH + (size_t)pin*Bc*Rc, w_hh, pgates,
                                     nullptr, pXg + (size_t)t*Bc*Gc,
                                     Bc, Gc, Rc, 0, 0);
        fused_step<<<Bc,512>>>(se_b, ho_b, al_W, al_b, a2h_b, t, pin, pout);
    }

    // One batched vocab projection, written in [b,t,v] layout (rows are t*B+b)
    tgemm<<<dim3((Vc+BN-1)/BN,(Tm*Bc)/BM),256>>>(pHout, lg_W, out, lg_b, nullptr,
                                                 Tm*Bc, Vc, Rc, 0, /*remap*/1);
    logsoftmax_kernel<<<Bc*Tm,256>>>(out);
}